// round 1
// baseline (speedup 1.0000x reference)
#include <cuda_runtime.h>
#include <math.h>

#define BSZ 4
#define SEQ 2048
#define DIM 2048
#define NHEADS 16
#define NKV 4
#define HD 128
#define KVD 512
#define NTOK (BSZ*SEQ)

// ---- scratch (static __device__ arrays: allocation-guard safe) ----
__device__ float g_q[(size_t)NTOK * DIM];   // 64 MB
__device__ float g_k[(size_t)NTOK * KVD];   // 16 MB
__device__ float g_v[(size_t)NTOK * KVD];   // 16 MB
__device__ float g_y[(size_t)NTOK * DIM];   // 64 MB

// =====================================================================
// SGEMM NT: C[M,N] = A[M,K] @ B[N,K]^T   (both operands K-contiguous)
// 128x128 block, BK=16, 256 threads, 8x8 register tile per thread.
// =====================================================================
#define BM 128
#define BN 128
#define BK 16
#define ASTR (BM + 4)

__global__ __launch_bounds__(256) void sgemm_nt_kernel(
    float* __restrict__ C, const float* __restrict__ A, const float* __restrict__ B,
    int M, int N, int K)
{
    __shared__ float As[BK][ASTR];
    __shared__ float Bs[BK][ASTR];
    const int tid = threadIdx.x;
    const int tx = tid & 15;
    const int ty = tid >> 4;
    const int bm = blockIdx.y * BM;
    const int bn = blockIdx.x * BN;
    const int lr = tid >> 2;          // 0..63
    const int lk = (tid & 3) << 2;    // 0,4,8,12

    const float* Ap = A + (size_t)bm * K;
    const float* Bp = B + (size_t)bn * K;

    float acc[8][8];
    #pragma unroll
    for (int i = 0; i < 8; i++)
        #pragma unroll
        for (int j = 0; j < 8; j++) acc[i][j] = 0.f;

    for (int k0 = 0; k0 < K; k0 += BK) {
        #pragma unroll
        for (int it = 0; it < 2; it++) {
            int row = lr + it * 64;
            float4 va = *(const float4*)(Ap + (size_t)row * K + k0 + lk);
            As[lk + 0][row] = va.x; As[lk + 1][row] = va.y;
            As[lk + 2][row] = va.z; As[lk + 3][row] = va.w;
            float4 vb = *(const float4*)(Bp + (size_t)row * K + k0 + lk);
            Bs[lk + 0][row] = vb.x; Bs[lk + 1][row] = vb.y;
            Bs[lk + 2][row] = vb.z; Bs[lk + 3][row] = vb.w;
        }
        __syncthreads();
        #pragma unroll
        for (int k = 0; k < BK; k++) {
            float a[8], b[8];
            *(float4*)&a[0] = *(const float4*)&As[k][ty * 4];
            *(float4*)&a[4] = *(const float4*)&As[k][ty * 4 + 64];
            *(float4*)&b[0] = *(const float4*)&Bs[k][tx * 4];
            *(float4*)&b[4] = *(const float4*)&Bs[k][tx * 4 + 64];
            #pragma unroll
            for (int i = 0; i < 8; i++)
                #pragma unroll
                for (int j = 0; j < 8; j++)
                    acc[i][j] = fmaf(a[i], b[j], acc[i][j]);
        }
        __syncthreads();
    }

    #pragma unroll
    for (int i = 0; i < 8; i++) {
        int row = bm + ty * 4 + (i & 3) + (i >> 2) * 64;
        float* Cp = C + (size_t)row * N + bn;
        *(float4*)(Cp + tx * 4)      = *(float4*)&acc[i][0];
        *(float4*)(Cp + tx * 4 + 64) = *(float4*)&acc[i][4];
    }
}

// =====================================================================
// Fused per-(token, head) RMSNorm + RoPE + optional gain.
// One 128-thread block per (token, head); head_dim = 128.
// =====================================================================
__global__ __launch_bounds__(128) void norm_rope_kernel(
    float* __restrict__ buf, int nheads, const float* __restrict__ gain)
{
    const int token = blockIdx.x / nheads;
    const int h = blockIdx.x - token * nheads;
    const int s = token & (SEQ - 1);     // position within sequence
    float* v = buf + (size_t)token * nheads * HD + (size_t)h * HD;
    const int d = threadIdx.x;

    float x = v[d];
    float ss = x * x;
    #pragma unroll
    for (int o = 16; o > 0; o >>= 1) ss += __shfl_xor_sync(0xffffffffu, ss, o);
    __shared__ float wsum[4];
    __shared__ float xn[HD];
    if ((d & 31) == 0) wsum[d >> 5] = ss;
    xn[d] = x;
    __syncthreads();
    float tot = wsum[0] + wsum[1] + wsum[2] + wsum[3];
    float r = rsqrtf(tot * (1.0f / HD) + 1.1920929e-7f);  // FLT_EPSILON

    if (d < 64) {
        float g = (gain != nullptr) ? gain[h] : 1.0f;
        // inv_freq = 10000^(-2d/128); compute in double, round to fp32 to match
        // jnp's correctly-rounded fp32 power.
        double e = (double)(-2.0 * d / (double)HD) * 9.210340371976184; // ln(10000)
        float invf = (float)exp(e);
        float fr = (float)s * invf;
        float c, sn;
        sincosf(fr, &sn, &c);
        float x1 = xn[d] * r;
        float x2 = xn[d + 64] * r;
        v[d]      = (x1 * c + x2 * sn) * g;
        v[d + 64] = (x2 * c - x1 * sn) * g;
    }
}

// =====================================================================
// Flash attention, fp32, causal, GQA (kv head = h/4).
// BM=BN=64, 128 threads. Online softmax. Causal tile skipping.
// Thread layout: tx = tid&15, ty = tid>>4.
//   QK phase : thread owns rows ty*8..+7, cols tx*4..+3 of the 64x64 score tile
//   PV phase : thread owns rows ty*8..+7, dims tx*8..+7 of the 64x128 output
// =====================================================================
#define FBM 64
#define FBN 64
#define QSTR 132     // 128 + 4 pad (keeps float4 alignment, breaks bank conflicts)
#define SSTR 68      // 64 + 4 pad

__global__ __launch_bounds__(128) void flash_kernel(
    float* __restrict__ Y, const float* __restrict__ Q,
    const float* __restrict__ Kb, const float* __restrict__ Vb)
{
    extern __shared__ float sm[];
    float* Qs   = sm;                    // [64][132]
    float* Ks   = Qs + FBM * QSTR;       // [64][132]
    float* Vs   = Ks + FBN * QSTR;       // [64][132]
    float* Ss   = Vs + FBN * QSTR;       // [64][68]
    float* rowm = Ss + FBM * SSTR;       // [64]
    float* rowl = rowm + FBM;            // [64]
    float* rowsc = rowl + FBM;           // [64]

    const int qtile = blockIdx.x;
    const int h = blockIdx.y;
    const int b = blockIdx.z;
    const int kvh = h >> 2;
    const int tid = threadIdx.x;
    const int tx = tid & 15;
    const int ty = tid >> 4;

    const float* Qp = Q  + (size_t)b * SEQ * DIM + (size_t)h * HD;
    const float* Kp = Kb + (size_t)b * SEQ * KVD + (size_t)kvh * HD;
    const float* Vp = Vb + (size_t)b * SEQ * KVD + (size_t)kvh * HD;

    const int q0 = qtile * FBM;
    for (int i = tid; i < FBM * 32; i += 128) {
        int r = i >> 5, c = (i & 31) << 2;
        *(float4*)&Qs[r * QSTR + c] = *(const float4*)(Qp + (size_t)(q0 + r) * DIM + c);
    }
    if (tid < FBM) { rowm[tid] = -INFINITY; rowl[tid] = 0.f; }

    float acc[8][8];
    #pragma unroll
    for (int i = 0; i < 8; i++)
        #pragma unroll
        for (int j = 0; j < 8; j++) acc[i][j] = 0.f;
    __syncthreads();

    const float scale = 0.088388347648318447f;   // 1/sqrt(128)

    for (int jt = 0; jt <= qtile; jt++) {
        const int k0 = jt * FBN;
        for (int i = tid; i < FBN * 32; i += 128) {
            int r = i >> 5, c = (i & 31) << 2;
            *(float4*)&Ks[r * QSTR + c] = *(const float4*)(Kp + (size_t)(k0 + r) * KVD + c);
            *(float4*)&Vs[r * QSTR + c] = *(const float4*)(Vp + (size_t)(k0 + r) * KVD + c);
        }
        __syncthreads();

        // ---- scores: 64x64 = QK^T over d=128 ----
        float sc[8][4];
        #pragma unroll
        for (int i = 0; i < 8; i++)
            #pragma unroll
            for (int j = 0; j < 4; j++) sc[i][j] = 0.f;

        #pragma unroll 4
        for (int d = 0; d < HD; d += 4) {
            float4 kf[4];
            #pragma unroll
            for (int j = 0; j < 4; j++)
                kf[j] = *(const float4*)&Ks[(tx * 4 + j) * QSTR + d];
            #pragma unroll
            for (int i = 0; i < 8; i++) {
                float4 qf = *(const float4*)&Qs[(ty * 8 + i) * QSTR + d];
                #pragma unroll
                for (int j = 0; j < 4; j++) {
                    sc[i][j] = fmaf(qf.x, kf[j].x, sc[i][j]);
                    sc[i][j] = fmaf(qf.y, kf[j].y, sc[i][j]);
                    sc[i][j] = fmaf(qf.z, kf[j].z, sc[i][j]);
                    sc[i][j] = fmaf(qf.w, kf[j].w, sc[i][j]);
                }
            }
        }

        const bool diag = (jt == qtile);
        #pragma unroll
        for (int i = 0; i < 8; i++) {
            int r = ty * 8 + i;
            #pragma unroll
            for (int j = 0; j < 4; j++) {
                int c = tx * 4 + j;
                float vsc = sc[i][j] * scale;
                if (diag && c > r) vsc = -INFINITY;
                sc[i][j] = vsc;
                Ss[r * SSTR + c] = vsc;
            }
        }
        __syncthreads();

        // ---- row max (64 threads, one per row) ----
        if (tid < FBM) {
            int r = tid;
            float m_old = rowm[r];
            float mx = m_old;
            #pragma unroll 4
            for (int c4 = 0; c4 < FBN; c4 += 4) {
                float4 sv = *(const float4*)&Ss[r * SSTR + c4];
                mx = fmaxf(mx, fmaxf(fmaxf(sv.x, sv.y), fmaxf(sv.z, sv.w)));
            }
            rowsc[r] = __expf(m_old - mx);
            rowm[r] = mx;
        }
        __syncthreads();

        // ---- exp (distributed across all 128 threads) + row-sum reduce ----
        float rs[8];
        #pragma unroll
        for (int i = 0; i < 8; i++) {
            int r = ty * 8 + i;
            float mx = rowm[r];
            float s0 = 0.f;
            #pragma unroll
            for (int j = 0; j < 4; j++) {
                float p = __expf(sc[i][j] - mx);
                Ss[r * SSTR + tx * 4 + j] = p;
                s0 += p;
            }
            rs[i] = s0;
        }
        #pragma unroll
        for (int i = 0; i < 8; i++) {
            float s0 = rs[i];
            #pragma unroll
            for (int o = 8; o > 0; o >>= 1) s0 += __shfl_xor_sync(0xffffffffu, s0, o);
            rs[i] = s0;
        }
        if (tx == 0) {
            #pragma unroll
            for (int i = 0; i < 8; i++) {
                int r = ty * 8 + i;
                rowl[r] = rowl[r] * rowsc[r] + rs[i];
            }
        }
        __syncthreads();

        // ---- rescale accumulators + P@V ----
        #pragma unroll
        for (int i = 0; i < 8; i++) {
            float scl = rowsc[ty * 8 + i];
            #pragma unroll
            for (int j = 0; j < 8; j++) acc[i][j] *= scl;
        }
        #pragma unroll 4
        for (int kk = 0; kk < FBN; kk++) {
            float4 v0 = *(const float4*)&Vs[kk * QSTR + tx * 8];
            float4 v1 = *(const float4*)&Vs[kk * QSTR + tx * 8 + 4];
            float p[8];
            #pragma unroll
            for (int i = 0; i < 8; i++) p[i] = Ss[(ty * 8 + i) * SSTR + kk];
            #pragma unroll
            for (int i = 0; i < 8; i++) {
                acc[i][0] = fmaf(p[i], v0.x, acc[i][0]);
                acc[i][1] = fmaf(p[i], v0.y, acc[i][1]);
                acc[i][2] = fmaf(p[i], v0.z, acc[i][2]);
                acc[i][3] = fmaf(p[i], v0.w, acc[i][3]);
                acc[i][4] = fmaf(p[i], v1.x, acc[i][4]);
                acc[i][5] = fmaf(p[i], v1.y, acc[i][5]);
                acc[i][6] = fmaf(p[i], v1.z, acc[i][6]);
                acc[i][7] = fmaf(p[i], v1.w, acc[i][7]);
            }
        }
        __syncthreads();
    }

    // ---- epilogue: divide by l, write Y[b,s,h*128+d] ----
    #pragma unroll
    for (int i = 0; i < 8; i++) {
        int r = ty * 8 + i;
        float inv = 1.0f / rowl[r];
        float4 o0, o1;
        o0.x = acc[i][0] * inv; o0.y = acc[i][1] * inv;
        o0.z = acc[i][2] * inv; o0.w = acc[i][3] * inv;
        o1.x = acc[i][4] * inv; o1.y = acc[i][5] * inv;
        o1.z = acc[i][6] * inv; o1.w = acc[i][7] * inv;
        float* Yp = Y + (size_t)(b * SEQ + q0 + r) * DIM + h * HD + tx * 8;
        *(float4*)Yp = o0;
        *(float4*)(Yp + 4) = o1;
    }
}

// =====================================================================
// kernel_launch
// =====================================================================
extern "C" void kernel_launch(void* const* d_in, const int* in_sizes, int n_in,
                              void* d_out, int out_size)
{
    const float* x  = (const float*)d_in[0];
    const float* Wq = (const float*)d_in[1];
    const float* Wk = (const float*)d_in[2];
    const float* Wv = (const float*)d_in[3];
    const float* Wo = (const float*)d_in[4];
    const float* qg = (const float*)d_in[5];
    float* out = (float*)d_out;

    float *qb, *kb, *vb, *yb;
    cudaGetSymbolAddress((void**)&qb, g_q);
    cudaGetSymbolAddress((void**)&kb, g_k);
    cudaGetSymbolAddress((void**)&vb, g_v);
    cudaGetSymbolAddress((void**)&yb, g_y);

    // QKV projections
    sgemm_nt_kernel<<<dim3(DIM / BN, NTOK / BM), 256>>>(qb, x, Wq, NTOK, DIM, DIM);
    sgemm_nt_kernel<<<dim3(KVD / BN, NTOK / BM), 256>>>(kb, x, Wk, NTOK, KVD, DIM);
    sgemm_nt_kernel<<<dim3(KVD / BN, NTOK / BM), 256>>>(vb, x, Wv, NTOK, KVD, DIM);

    // RMSNorm + RoPE (+ gain for Q)
    norm_rope_kernel<<<NTOK * NHEADS, 128>>>(qb, NHEADS, qg);
    norm_rope_kernel<<<NTOK * NKV, 128>>>(kb, NKV, nullptr);

    // Flash attention
    size_t fsm = (size_t)(3 * FBM * QSTR + FBM * SSTR + 3 * FBM) * sizeof(float);
    cudaFuncSetAttribute(flash_kernel, cudaFuncAttributeMaxDynamicSharedMemorySize, (int)fsm);
    flash_kernel<<<dim3(SEQ / FBM, NHEADS, BSZ), 128, fsm>>>(yb, qb, kb, vb);

    // Output projection
    sgemm_nt_kernel<<<dim3(DIM / BN, NTOK / BM), 256>>>(out, yb, Wo, NTOK, DIM, DIM);
}

// round 3
// speedup vs baseline: 1.9223x; 1.9223x over previous
#include <cuda_runtime.h>
#include <cuda_bf16.h>
#include <math.h>
#include <cstdint>

#define BSZ 4
#define SEQ 2048
#define DIM 2048
#define NHEADS 16
#define NKV 4
#define HD 128
#define KVD 512
#define NTOK (BSZ*SEQ)
#define GK 2048            // shared K dim of all projections

#if !defined(__CUDA_ARCH__) || defined(__CUDA_ARCH_FEAT_SM103_ALL) || defined(__CUDA_ARCH_FEAT_SM100_ALL)
#define HAS_TCGEN05 1
#else
#define HAS_TCGEN05 0
#endif

// ---------------- scratch (__device__ globals: allocation-guard safe) ----
__device__ float g_q[(size_t)NTOK * DIM];
__device__ float g_k[(size_t)NTOK * KVD];
__device__ float g_v[(size_t)NTOK * KVD];
__device__ float g_y[(size_t)NTOK * DIM];
__device__ __nv_bfloat16 g_xhi[(size_t)NTOK * DIM];
__device__ __nv_bfloat16 g_xlo[(size_t)NTOK * DIM];
__device__ __nv_bfloat16 g_yhi[(size_t)NTOK * DIM];
__device__ __nv_bfloat16 g_ylo[(size_t)NTOK * DIM];
__device__ __nv_bfloat16 g_wqhi[(size_t)DIM * DIM];
__device__ __nv_bfloat16 g_wqlo[(size_t)DIM * DIM];
__device__ __nv_bfloat16 g_wkhi[(size_t)KVD * DIM];
__device__ __nv_bfloat16 g_wklo[(size_t)KVD * DIM];
__device__ __nv_bfloat16 g_wvhi[(size_t)KVD * DIM];
__device__ __nv_bfloat16 g_wvlo[(size_t)KVD * DIM];
__device__ __nv_bfloat16 g_wohi[(size_t)DIM * DIM];
__device__ __nv_bfloat16 g_wolo[(size_t)DIM * DIM];
__device__ float g_cos[SEQ * 64];
__device__ float g_sin[SEQ * 64];

// ---------------- PTX helpers (baseline ISA, safe on compute_103) --------
__device__ __forceinline__ uint32_t smem_u32(const void* p) {
    uint32_t a;
    asm("{ .reg .u64 t; cvta.to.shared.u64 t, %1; cvt.u32.u64 %0, t; }" : "=r"(a) : "l"(p));
    return a;
}
#define SWZ(o) ((o) ^ (((o) >> 3) & 0x70))

#define CP_ASYNC16(dst, src) \
    asm volatile("cp.async.cg.shared.global [%0], [%1], 16;" :: "r"(dst), "l"(src) : "memory")
#define CP_COMMIT() asm volatile("cp.async.commit_group;" ::: "memory")
#define CP_WAIT(n)  asm volatile("cp.async.wait_group %0;" :: "n"(n) : "memory")

#define MBAR_INIT(a, c) \
    asm volatile("mbarrier.init.shared.b64 [%0], %1;" :: "r"(a), "r"(c) : "memory")
#define MBAR_WAIT(a, ph) do { \
    uint32_t _m = (a), _p = (ph), _d; \
    asm volatile("{\n .reg .pred p;\n mbarrier.try_wait.parity.acquire.cta.shared::cta.b64 p, [%1], %2;\n selp.b32 %0,1,0,p;\n}" \
        : "=r"(_d) : "r"(_m), "r"(_p) : "memory"); \
    if (!_d) { \
        asm volatile("{\n .reg .pred P1;\nWL%=:\n mbarrier.try_wait.parity.acquire.cta.shared::cta.b64 P1, [%0], %1, 0x989680;\n @P1 bra.uni WD%=;\n bra.uni WL%=;\nWD%=:\n}" \
            :: "r"(_m), "r"(_p) : "memory"); \
    } } while (0)

#define FENCE_PROXY_ASYNC() asm volatile("fence.proxy.async.shared::cta;" ::: "memory")

// =====================================================================
// bf16x3 tcgen05 GEMM:  C[M,N](fp32) = (Ahi+Alo)[M,K] @ (Bhi+Blo)[N,K]^T
// Tile 128x128, K-chunks of 64 bf16 (one SW128 atom column), 3 passes
// (hi*hi, lo*hi, hi*lo) accumulated in TMEM, 4-stage cp.async pipeline.
// =====================================================================
#define TM 128
#define TN 128
#define KC 64
#define NST 4
#define KCH (GK / KC)          // 32
#define NCHUNK (3 * KCH)       // 96
#define STAGE_BYTES (TM * 128 + TN * 128)   // 32 KB
#define GEMM_SMEM (2048 + NST * STAGE_BYTES)
#define GEMM_IDESC ((1u<<4) | (1u<<7) | (1u<<10) | ((TN/8)<<17) | ((TM/16)<<24))

#if HAS_TCGEN05

// ---- tcgen05 wrappers (sm_103a-only pass) ----
__device__ __forceinline__ uint32_t elect1() {
    uint32_t p;
    asm volatile("{.reg .pred P; elect.sync _|P, 0xFFFFFFFF; selp.b32 %0,1,0,P;}" : "=r"(p));
    return p;
}
#define TCGEN05_ALLOC(smem_addr, ncols) \
    asm volatile("tcgen05.alloc.cta_group::1.sync.aligned.shared::cta.b32 [%0], %1;" \
        :: "r"(smem_addr), "r"(ncols) : "memory")
#define TCGEN05_RELINQ() \
    asm volatile("tcgen05.relinquish_alloc_permit.cta_group::1.sync.aligned;")
#define TCGEN05_DEALLOC(tmem, ncols) \
    asm volatile("tcgen05.dealloc.cta_group::1.sync.aligned.b32 %0, %1;" :: "r"(tmem), "r"(ncols))
#define TCGEN05_COMMIT(mbar) \
    asm volatile("tcgen05.commit.cta_group::1.mbarrier::arrive::one.shared::cluster.b64 [%0];" \
        :: "r"(mbar) : "memory")
#define TCGEN05_FENCE_AFTER() asm volatile("tcgen05.fence::after_thread_sync;" ::: "memory")
#define TCGEN05_WAIT_LD() asm volatile("tcgen05.wait::ld.sync.aligned;" ::: "memory")

#define LDTM_X32(r, a) \
    asm volatile("tcgen05.ld.sync.aligned.32x32b.x32.b32 " \
        "{%0,%1,%2,%3,%4,%5,%6,%7,%8,%9,%10,%11,%12,%13,%14,%15," \
        "%16,%17,%18,%19,%20,%21,%22,%23,%24,%25,%26,%27,%28,%29,%30,%31}, [%32];" \
        : "=r"((r)[0]),"=r"((r)[1]),"=r"((r)[2]),"=r"((r)[3]),"=r"((r)[4]),"=r"((r)[5]),"=r"((r)[6]),"=r"((r)[7]), \
          "=r"((r)[8]),"=r"((r)[9]),"=r"((r)[10]),"=r"((r)[11]),"=r"((r)[12]),"=r"((r)[13]),"=r"((r)[14]),"=r"((r)[15]), \
          "=r"((r)[16]),"=r"((r)[17]),"=r"((r)[18]),"=r"((r)[19]),"=r"((r)[20]),"=r"((r)[21]),"=r"((r)[22]),"=r"((r)[23]), \
          "=r"((r)[24]),"=r"((r)[25]),"=r"((r)[26]),"=r"((r)[27]),"=r"((r)[28]),"=r"((r)[29]),"=r"((r)[30]),"=r"((r)[31]) \
        : "r"(a))

__device__ __forceinline__ uint64_t mk_desc(uint32_t addr) {
    const uint64_t base = (uint64_t(2) << 61) | (uint64_t(1) << 46) |
                          (uint64_t(64) << 32) | (uint64_t(1) << 16);   // SW128, LBO=1, SBO=64
    return base | ((addr >> 4) & 0x3FFF);
}
__device__ __forceinline__ void mma_bf16_ss(uint32_t d, uint64_t ad, uint64_t bd,
                                            uint32_t idesc, uint32_t en) {
    asm volatile("{\n .reg .pred p;\n setp.ne.u32 p, %4, 0;\n"
        " tcgen05.mma.cta_group::1.kind::f16 [%0], %1, %2, %3, {%5,%5,%5,%5}, p;\n}"
        :: "r"(d), "l"(ad), "l"(bd), "r"(idesc), "r"(en), "r"(0u) : "memory");
}

__global__ __launch_bounds__(128, 1)
void gemm_bf16x3_kernel(
    float* __restrict__ C,
    const __nv_bfloat16* __restrict__ Ahi, const __nv_bfloat16* __restrict__ Alo,
    const __nv_bfloat16* __restrict__ Bhi, const __nv_bfloat16* __restrict__ Blo,
    int N)
{
    extern __shared__ char sm[];
    const uint32_t sbase = smem_u32(sm);
    const uint32_t mbar0 = sbase + 8;                       // 4 mbars @ +8..+39
    const uint32_t tile0 = (sbase + 64 + 1023) & ~1023u;    // 1KB-aligned stage base
    const int tid = threadIdx.x, wid = tid >> 5, lid = tid & 31;
    const int bm = blockIdx.y * TM, bn = blockIdx.x * TN;

    if (tid == 0) {
        #pragma unroll
        for (int s = 0; s < NST; s++) MBAR_INIT(mbar0 + s * 8, 1);
    }
    if (wid == 0) { TCGEN05_ALLOC(sbase, 128); TCGEN05_RELINQ(); }
    __syncthreads();
    uint32_t tmem;
    asm volatile("ld.shared.b32 %0, [%1];" : "=r"(tmem) : "r"(sbase));

    // per-thread load mapping: 8 granules of 16B per operand per chunk
    const int row = tid >> 3;            // base row for i=0 (rows tid/8 + i*16)
    const int seg = tid & 7;

    auto load_chunk = [&](int c) {
        int pass = (c >= 2 * KCH) ? 2 : (c >= KCH ? 1 : 0);
        int kc = c - pass * KCH;
        const __nv_bfloat16* Ab = (pass == 1) ? Alo : Ahi;
        const __nv_bfloat16* Bb = (pass == 2) ? Blo : Bhi;
        uint32_t sA = tile0 + (c & (NST - 1)) * STAGE_BYTES;
        uint32_t sB = sA + TM * 128;
        const char* ap = (const char*)Ab + (size_t)(bm + row) * (GK * 2) + kc * 128 + seg * 16;
        const char* bp = (const char*)Bb + (size_t)(bn + row) * (GK * 2) + kc * 128 + seg * 16;
        #pragma unroll
        for (int i = 0; i < 8; i++) {
            uint32_t off = (row + i * 16) * 128 + seg * 16;
            uint32_t so = SWZ(off);
            CP_ASYNC16(sA + so, ap + (size_t)i * 16 * (GK * 2));
            CP_ASYNC16(sB + so, bp + (size_t)i * 16 * (GK * 2));
        }
    };

    #pragma unroll
    for (int c = 0; c < NST - 1; c++) { load_chunk(c); CP_COMMIT(); }

    for (int c = 0; c < NCHUNK; c++) {
        const int cl = c + NST - 1;
        if (cl < NCHUNK) {
            if (cl >= NST) MBAR_WAIT(mbar0 + (cl & (NST - 1)) * 8, ((cl >> 2) + 1) & 1);
            load_chunk(cl);
        }
        CP_COMMIT();
        CP_WAIT(NST - 1);
        FENCE_PROXY_ASYNC();
        __syncthreads();
        if (wid == 0 && elect1()) {
            uint32_t sA = tile0 + (c & (NST - 1)) * STAGE_BYTES;
            uint64_t ad = mk_desc(sA), bd = mk_desc(sA + TM * 128);
            #pragma unroll
            for (int s = 0; s < 4; s++)     // 4 x K=16 sub-MMAs cover KC=64
                mma_bf16_ss(tmem, ad + s * 2, bd + s * 2, GEMM_IDESC,
                            (uint32_t)((c | s) != 0));
            TCGEN05_COMMIT(mbar0 + (c & (NST - 1)) * 8);
        }
    }

    // epilogue
    MBAR_WAIT(mbar0 + ((NCHUNK - 1) & (NST - 1)) * 8, ((NCHUNK - 1) >> 2) & 1);
    TCGEN05_FENCE_AFTER();
    #pragma unroll
    for (int cb = 0; cb < TN; cb += 32) {
        uint32_t r[32];
        LDTM_X32(r, tmem + cb);
        TCGEN05_WAIT_LD();
        float* Cp = C + (size_t)(bm + wid * 32 + lid) * N + bn + cb;
        #pragma unroll
        for (int j = 0; j < 8; j++) {
            float4 v;
            v.x = __uint_as_float(r[j * 4 + 0]); v.y = __uint_as_float(r[j * 4 + 1]);
            v.z = __uint_as_float(r[j * 4 + 2]); v.w = __uint_as_float(r[j * 4 + 3]);
            *(float4*)(Cp + j * 4) = v;
        }
    }
    __syncthreads();
    if (wid == 0) TCGEN05_DEALLOC(tmem, 128);
}

#else  // !HAS_TCGEN05 — correct fallback for the generic compute_103 PTX pass.
// Never executed on GB300 (driver selects the sm_103a SASS), but keeps the
// non-accelerated PTX valid and semantically correct.
__global__ __launch_bounds__(128, 1)
void gemm_bf16x3_kernel(
    float* __restrict__ C,
    const __nv_bfloat16* __restrict__ Ahi, const __nv_bfloat16* __restrict__ Alo,
    const __nv_bfloat16* __restrict__ Bhi, const __nv_bfloat16* __restrict__ Blo,
    int N)
{
    const int m = blockIdx.y * TM + threadIdx.x;
    const int n0 = blockIdx.x * TN;
    for (int n = n0; n < n0 + TN; n++) {
        float s = 0.f;
        for (int k = 0; k < GK; k++) {
            float a = __bfloat162float(Ahi[(size_t)m * GK + k]) +
                      __bfloat162float(Alo[(size_t)m * GK + k]);
            float b = __bfloat162float(Bhi[(size_t)n * GK + k]) +
                      __bfloat162float(Blo[(size_t)n * GK + k]);
            s = fmaf(a, b, s);
        }
        C[(size_t)m * N + n] = s;
    }
}
#endif // HAS_TCGEN05

// =====================================================================
// fp32 -> (bf16 hi, bf16 lo) split
// =====================================================================
__global__ __launch_bounds__(256) void split_kernel(
    const float* __restrict__ src, __nv_bfloat16* __restrict__ hi,
    __nv_bfloat16* __restrict__ lo, int n4)
{
    int i = blockIdx.x * 256 + threadIdx.x;
    if (i >= n4) return;
    float4 v = ((const float4*)src)[i];
    __nv_bfloat16 h0 = __float2bfloat16(v.x), h1 = __float2bfloat16(v.y);
    __nv_bfloat16 h2 = __float2bfloat16(v.z), h3 = __float2bfloat16(v.w);
    __nv_bfloat162* H = (__nv_bfloat162*)hi;
    __nv_bfloat162* L = (__nv_bfloat162*)lo;
    H[i * 2 + 0] = __nv_bfloat162(h0, h1);
    H[i * 2 + 1] = __nv_bfloat162(h2, h3);
    L[i * 2 + 0] = __nv_bfloat162(__float2bfloat16(v.x - __bfloat162float(h0)),
                                  __float2bfloat16(v.y - __bfloat162float(h1)));
    L[i * 2 + 1] = __nv_bfloat162(__float2bfloat16(v.z - __bfloat162float(h2)),
                                  __float2bfloat16(v.w - __bfloat162float(h3)));
}

// =====================================================================
// RoPE cos/sin table: [SEQ][64]
// =====================================================================
__global__ __launch_bounds__(256) void rope_table_kernel()
{
    int idx = blockIdx.x * 256 + threadIdx.x;
    if (idx >= SEQ * 64) return;
    int s = idx >> 6, d = idx & 63;
    double e = (double)(-2.0 * d / (double)HD) * 9.210340371976184;  // ln(10000)
    float invf = (float)exp(e);
    float fr = (float)s * invf;
    float c, sn;
    sincosf(fr, &sn, &c);
    g_cos[idx] = c;
    g_sin[idx] = sn;
}

// =====================================================================
// Fused RMSNorm + RoPE (+gain) per (token, head)
// =====================================================================
__global__ __launch_bounds__(128) void norm_rope_kernel(
    float* __restrict__ buf, int nheads, const float* __restrict__ gain)
{
    const int token = blockIdx.x / nheads;
    const int h = blockIdx.x - token * nheads;
    const int s = token & (SEQ - 1);
    float* v = buf + (size_t)token * nheads * HD + (size_t)h * HD;
    const int d = threadIdx.x;

    float x = v[d];
    float ss = x * x;
    #pragma unroll
    for (int o = 16; o > 0; o >>= 1) ss += __shfl_xor_sync(0xffffffffu, ss, o);
    __shared__ float wsum[4];
    __shared__ float xn[HD];
    if ((d & 31) == 0) wsum[d >> 5] = ss;
    xn[d] = x;
    __syncthreads();
    float tot = wsum[0] + wsum[1] + wsum[2] + wsum[3];
    float r = rsqrtf(tot * (1.0f / HD) + 1.1920929e-7f);

    if (d < 64) {
        float g = (gain != nullptr) ? gain[h] : 1.0f;
        float c = g_cos[s * 64 + d];
        float sn = g_sin[s * 64 + d];
        float x1 = xn[d] * r;
        float x2 = xn[d + 64] * r;
        v[d]      = (x1 * c + x2 * sn) * g;
        v[d + 64] = (x2 * c - x1 * sn) * g;
    }
}

// =====================================================================
// Flash attention, fp32, causal, GQA
// =====================================================================
#define FBM 64
#define FBN 64
#define QSTR 132
#define SSTR 68

__global__ __launch_bounds__(128) void flash_kernel(
    float* __restrict__ Y, const float* __restrict__ Q,
    const float* __restrict__ Kb, const float* __restrict__ Vb)
{
    extern __shared__ float smf[];
    float* Qs   = smf;
    float* Ks   = Qs + FBM * QSTR;
    float* Vs   = Ks + FBN * QSTR;
    float* Ss   = Vs + FBN * QSTR;
    float* rowm = Ss + FBM * SSTR;
    float* rowl = rowm + FBM;
    float* rowsc = rowl + FBM;

    const int qtile = blockIdx.x;
    const int h = blockIdx.y;
    const int b = blockIdx.z;
    const int kvh = h >> 2;
    const int tid = threadIdx.x;
    const int tx = tid & 15;
    const int ty = tid >> 4;

    const float* Qp = Q  + (size_t)b * SEQ * DIM + (size_t)h * HD;
    const float* Kp = Kb + (size_t)b * SEQ * KVD + (size_t)kvh * HD;
    const float* Vp = Vb + (size_t)b * SEQ * KVD + (size_t)kvh * HD;

    const int q0 = qtile * FBM;
    for (int i = tid; i < FBM * 32; i += 128) {
        int r = i >> 5, c = (i & 31) << 2;
        *(float4*)&Qs[r * QSTR + c] = *(const float4*)(Qp + (size_t)(q0 + r) * DIM + c);
    }
    if (tid < FBM) { rowm[tid] = -INFINITY; rowl[tid] = 0.f; }

    float acc[8][8];
    #pragma unroll
    for (int i = 0; i < 8; i++)
        #pragma unroll
        for (int j = 0; j < 8; j++) acc[i][j] = 0.f;
    __syncthreads();

    const float scale = 0.088388347648318447f;

    for (int jt = 0; jt <= qtile; jt++) {
        const int k0 = jt * FBN;
        for (int i = tid; i < FBN * 32; i += 128) {
            int r = i >> 5, c = (i & 31) << 2;
            *(float4*)&Ks[r * QSTR + c] = *(const float4*)(Kp + (size_t)(k0 + r) * KVD + c);
            *(float4*)&Vs[r * QSTR + c] = *(const float4*)(Vp + (size_t)(k0 + r) * KVD + c);
        }
        __syncthreads();

        float sc[8][4];
        #pragma unroll
        for (int i = 0; i < 8; i++)
            #pragma unroll
            for (int j = 0; j < 4; j++) sc[i][j] = 0.f;

        #pragma unroll 4
        for (int d = 0; d < HD; d += 4) {
            float4 kf[4];
            #pragma unroll
            for (int j = 0; j < 4; j++)
                kf[j] = *(const float4*)&Ks[(tx * 4 + j) * QSTR + d];
            #pragma unroll
            for (int i = 0; i < 8; i++) {
                float4 qf = *(const float4*)&Qs[(ty * 8 + i) * QSTR + d];
                #pragma unroll
                for (int j = 0; j < 4; j++) {
                    sc[i][j] = fmaf(qf.x, kf[j].x, sc[i][j]);
                    sc[i][j] = fmaf(qf.y, kf[j].y, sc[i][j]);
                    sc[i][j] = fmaf(qf.z, kf[j].z, sc[i][j]);
                    sc[i][j] = fmaf(qf.w, kf[j].w, sc[i][j]);
                }
            }
        }

        const bool diag = (jt == qtile);
        #pragma unroll
        for (int i = 0; i < 8; i++) {
            int r = ty * 8 + i;
            #pragma unroll
            for (int j = 0; j < 4; j++) {
                int c = tx * 4 + j;
                float vsc = sc[i][j] * scale;
                if (diag && c > r) vsc = -INFINITY;
                sc[i][j] = vsc;
                Ss[r * SSTR + c] = vsc;
            }
        }
        __syncthreads();

        if (tid < FBM) {
            int r = tid;
            float m_old = rowm[r];
            float mx = m_old;
            #pragma unroll 4
            for (int c4 = 0; c4 < FBN; c4 += 4) {
                float4 sv = *(const float4*)&Ss[r * SSTR + c4];
                mx = fmaxf(mx, fmaxf(fmaxf(sv.x, sv.y), fmaxf(sv.z, sv.w)));
            }
            rowsc[r] = __expf(m_old - mx);
            rowm[r] = mx;
        }
        __syncthreads();

        float rs[8];
        #pragma unroll
        for (int i = 0; i < 8; i++) {
            int r = ty * 8 + i;
            float mx = rowm[r];
            float s0 = 0.f;
            #pragma unroll
            for (int j = 0; j < 4; j++) {
                float p = __expf(sc[i][j] - mx);
                Ss[r * SSTR + tx * 4 + j] = p;
                s0 += p;
            }
            rs[i] = s0;
        }
        #pragma unroll
        for (int i = 0; i < 8; i++) {
            float s0 = rs[i];
            #pragma unroll
            for (int o = 8; o > 0; o >>= 1) s0 += __shfl_xor_sync(0xffffffffu, s0, o);
            rs[i] = s0;
        }
        if (tx == 0) {
            #pragma unroll
            for (int i = 0; i < 8; i++) {
                int r = ty * 8 + i;
                rowl[r] = rowl[r] * rowsc[r] + rs[i];
            }
        }
        __syncthreads();

        #pragma unroll
        for (int i = 0; i < 8; i++) {
            float scl = rowsc[ty * 8 + i];
            #pragma unroll
            for (int j = 0; j < 8; j++) acc[i][j] *= scl;
        }
        #pragma unroll 4
        for (int kk = 0; kk < FBN; kk++) {
            float4 v0 = *(const float4*)&Vs[kk * QSTR + tx * 8];
            float4 v1 = *(const float4*)&Vs[kk * QSTR + tx * 8 + 4];
            float p[8];
            #pragma unroll
            for (int i = 0; i < 8; i++) p[i] = Ss[(ty * 8 + i) * SSTR + kk];
            #pragma unroll
            for (int i = 0; i < 8; i++) {
                acc[i][0] = fmaf(p[i], v0.x, acc[i][0]);
                acc[i][1] = fmaf(p[i], v0.y, acc[i][1]);
                acc[i][2] = fmaf(p[i], v0.z, acc[i][2]);
                acc[i][3] = fmaf(p[i], v0.w, acc[i][3]);
                acc[i][4] = fmaf(p[i], v1.x, acc[i][4]);
                acc[i][5] = fmaf(p[i], v1.y, acc[i][5]);
                acc[i][6] = fmaf(p[i], v1.z, acc[i][6]);
                acc[i][7] = fmaf(p[i], v1.w, acc[i][7]);
            }
        }
        __syncthreads();
    }

    #pragma unroll
    for (int i = 0; i < 8; i++) {
        int r = ty * 8 + i;
        float inv = 1.0f / rowl[r];
        float4 o0, o1;
        o0.x = acc[i][0] * inv; o0.y = acc[i][1] * inv;
        o0.z = acc[i][2] * inv; o0.w = acc[i][3] * inv;
        o1.x = acc[i][4] * inv; o1.y = acc[i][5] * inv;
        o1.z = acc[i][6] * inv; o1.w = acc[i][7] * inv;
        float* Yp = Y + (size_t)(b * SEQ + q0 + r) * DIM + h * HD + tx * 8;
        *(float4*)Yp = o0;
        *(float4*)(Yp + 4) = o1;
    }
}

// =====================================================================
// kernel_launch
// =====================================================================
extern "C" void kernel_launch(void* const* d_in, const int* in_sizes, int n_in,
                              void* d_out, int out_size)
{
    const float* x  = (const float*)d_in[0];
    const float* Wq = (const float*)d_in[1];
    const float* Wk = (const float*)d_in[2];
    const float* Wv = (const float*)d_in[3];
    const float* Wo = (const float*)d_in[4];
    const float* qg = (const float*)d_in[5];
    float* out = (float*)d_out;

    float *qb, *kb, *vb, *yb;
    __nv_bfloat16 *xhi, *xlo, *yhi, *ylo, *wqh, *wql, *wkh, *wkl, *wvh, *wvl, *woh, *wol;
    cudaGetSymbolAddress((void**)&qb, g_q);
    cudaGetSymbolAddress((void**)&kb, g_k);
    cudaGetSymbolAddress((void**)&vb, g_v);
    cudaGetSymbolAddress((void**)&yb, g_y);
    cudaGetSymbolAddress((void**)&xhi, g_xhi);
    cudaGetSymbolAddress((void**)&xlo, g_xlo);
    cudaGetSymbolAddress((void**)&yhi, g_yhi);
    cudaGetSymbolAddress((void**)&ylo, g_ylo);
    cudaGetSymbolAddress((void**)&wqh, g_wqhi);
    cudaGetSymbolAddress((void**)&wql, g_wqlo);
    cudaGetSymbolAddress((void**)&wkh, g_wkhi);
    cudaGetSymbolAddress((void**)&wkl, g_wklo);
    cudaGetSymbolAddress((void**)&wvh, g_wvhi);
    cudaGetSymbolAddress((void**)&wvl, g_wvlo);
    cudaGetSymbolAddress((void**)&woh, g_wohi);
    cudaGetSymbolAddress((void**)&wol, g_wolo);

    cudaFuncSetAttribute(gemm_bf16x3_kernel,
                         cudaFuncAttributeMaxDynamicSharedMemorySize, GEMM_SMEM);

    // splits
    {
        int n4 = NTOK * DIM / 4;
        split_kernel<<<(n4 + 255) / 256, 256>>>(x, xhi, xlo, n4);
        int w4 = DIM * DIM / 4;
        split_kernel<<<(w4 + 255) / 256, 256>>>(Wq, wqh, wql, w4);
        split_kernel<<<(w4 + 255) / 256, 256>>>(Wo, woh, wol, w4);
        int k4 = KVD * DIM / 4;
        split_kernel<<<(k4 + 255) / 256, 256>>>(Wk, wkh, wkl, k4);
        split_kernel<<<(k4 + 255) / 256, 256>>>(Wv, wvh, wvl, k4);
    }
    rope_table_kernel<<<(SEQ * 64 + 255) / 256, 256>>>();

    // projections (tcgen05 bf16x3)
    gemm_bf16x3_kernel<<<dim3(DIM / TN, NTOK / TM), 128, GEMM_SMEM>>>(qb, xhi, xlo, wqh, wql, DIM);
    gemm_bf16x3_kernel<<<dim3(KVD / TN, NTOK / TM), 128, GEMM_SMEM>>>(kb, xhi, xlo, wkh, wkl, KVD);
    gemm_bf16x3_kernel<<<dim3(KVD / TN, NTOK / TM), 128, GEMM_SMEM>>>(vb, xhi, xlo, wvh, wvl, KVD);

    // norm + rope
    norm_rope_kernel<<<NTOK * NHEADS, 128>>>(qb, NHEADS, qg);
    norm_rope_kernel<<<NTOK * NKV, 128>>>(kb, NKV, nullptr);

    // flash attention
    size_t fsm = (size_t)(3 * FBM * QSTR + FBM * SSTR + 3 * FBM) * sizeof(float);
    cudaFuncSetAttribute(flash_kernel, cudaFuncAttributeMaxDynamicSharedMemorySize, (int)fsm);
    flash_kernel<<<dim3(SEQ / FBM, NHEADS, BSZ), 128, fsm>>>(yb, qb, kb, vb);

    // output projection
    {
        int n4 = NTOK * DIM / 4;
        split_kernel<<<(n4 + 255) / 256, 256>>>(yb, yhi, ylo, n4);
    }
    gemm_bf16x3_kernel<<<dim3(DIM / TN, NTOK / TM), 128, GEMM_SMEM>>>(out, yhi, ylo, woh, wol, DIM);
}